// round 6
// baseline (speedup 1.0000x reference)
#include <cuda_runtime.h>
#include <cuda_bf16.h>
#include <cstdint>
#include <math.h>

#define T_ 5
#define H_ 64
#define W_ 96
#define HW_ (H_ * W_)
#define HEADS_ 8
#define LVLS_ 5
#define PTS_ 4
#define NPIX_ (T_ * HW_)
#define PW_ (W_ + 2)            // 98
#define PH_ (H_ + 2)            // 66
#define PPIX_ (PW_ * PH_)       // 6468

// ================= helpers =================
__device__ __forceinline__ uint32_t smem_u32(const void* p) {
    uint32_t a;
    asm("{ .reg .u64 t; cvta.to.shared.u64 t, %1; cvt.u32.u64 %0, t; }" : "=r"(a) : "l"(p));
    return a;
}
__device__ __forceinline__ void ldsm4(uint32_t* r, uint32_t addr) {
    asm volatile("ldmatrix.sync.aligned.m8n8.x4.shared.b16 {%0,%1,%2,%3}, [%4];"
        : "=r"(r[0]), "=r"(r[1]), "=r"(r[2]), "=r"(r[3]) : "r"(addr));
}
__device__ __forceinline__ void mma16816(float* c, const uint32_t* a, uint32_t b0, uint32_t b1) {
    asm volatile(
        "mma.sync.aligned.m16n8k16.row.col.f32.bf16.bf16.f32 "
        "{%0,%1,%2,%3}, {%4,%5,%6,%7}, {%8,%9}, {%0,%1,%2,%3};"
        : "+f"(c[0]), "+f"(c[1]), "+f"(c[2]), "+f"(c[3])
        : "r"(a[0]), "r"(a[1]), "r"(a[2]), "r"(a[3]), "r"(b0), "r"(b1));
}

// ================= scratch =================
__device__ __align__(16) __nv_bfloat16 g_xfh[(size_t)T_ * PPIX_ * 256], g_xfl[(size_t)T_ * PPIX_ * 256];
__device__ __align__(16) __nv_bfloat16 g_xqh[(size_t)T_ * PPIX_ * 256], g_xql[(size_t)T_ * PPIX_ * 256];
__device__ __align__(16) __nv_bfloat16 g_xsh[(size_t)T_ * PPIX_ * 256], g_xsl[(size_t)T_ * PPIX_ * 256];
__device__ __align__(16) __nv_bfloat16 g_wvh[9 * 256 * 256], g_wvl[9 * 256 * 256];
__device__ __align__(16) __nv_bfloat16 g_wph[9 * 512 * 256], g_wpl[9 * 512 * 256];   // off+attn fused
__device__ __align__(16) __nv_bfloat16 g_wuh[9 * 256 * 256], g_wul[9 * 256 * 256];
__device__ float g_value[(size_t)T_ * HEADS_ * HW_ * 32];   // [t][head][pix][dh]
__device__ float g_off  [(size_t)T_ * 320 * HW_];
__device__ float g_attn [(size_t)T_ * 160 * HW_];
__device__ float g_adds [(size_t)4 * 5 * 2 * HW_];

// ================= border zeroing of padded buffers (ALL 256 channels) =================
__global__ void zero_border_kernel()
{
    int idx = blockIdx.x * 256 + threadIdx.x;          // [t][ppix][c32]
    if (idx >= T_ * PPIX_ * 32) return;
    int c32 = idx & 31;
    int pp  = (idx >> 5) % PPIX_;
    int t   = idx / (PPIX_ * 32);
    int py = pp / PW_, px = pp - py * PW_;
    if (py == 0 || py == PH_ - 1 || px == 0 || px == PW_ - 1) {
        size_t o = ((size_t)t * PPIX_ + pp) * 256 + c32 * 8;
        uint4 z = make_uint4(0, 0, 0, 0);
        *(uint4*)((char*)g_xfh + o * 2) = z; *(uint4*)((char*)g_xfl + o * 2) = z;
        *(uint4*)((char*)g_xqh + o * 2) = z; *(uint4*)((char*)g_xql + o * 2) = z;
        *(uint4*)((char*)g_xsh + o * 2) = z; *(uint4*)((char*)g_xsl + o * 2) = z;
    }
}

// ================= input transpose + bf16 hi/lo split (interior) =================
__global__ void __launch_bounds__(128) prep_x_kernel(
    const float* __restrict__ src, __nv_bfloat16* __restrict__ dh, __nv_bfloat16* __restrict__ dl)
{
    const int y = blockIdx.x, t = blockIdx.y, tid = threadIdx.x;
    __shared__ float s[64][97];
    for (int cib = 0; cib < 4; cib++) {
        __syncthreads();
        for (int i = tid; i < 64 * 96; i += 128) {
            int r = i / 96, c = i - r * 96;
            s[r][c] = src[((size_t)(t * 256 + cib * 64 + r)) * HW_ + y * 96 + c];
        }
        __syncthreads();
        if (tid < 96) {
            size_t ob = ((size_t)t * PPIX_ + (size_t)(y + 1) * PW_ + tid + 1) * 256 + cib * 64;
#pragma unroll 8
            for (int ci = 0; ci < 64; ci++) {
                float v = s[ci][tid];
                __nv_bfloat16 h = __float2bfloat16(v);
                dh[ob + ci] = h;
                dl[ob + ci] = __float2bfloat16(v - __bfloat162float(h));
            }
        }
    }
}

// weights [co][256][3][3] fp32 (x2 sources) -> [shift][CoPad][256] bf16 hi/lo
__global__ void prep_w_kernel(const float* __restrict__ w1, int C1,
                              const float* __restrict__ w2, int C2, int CoPad,
                              __nv_bfloat16* __restrict__ dh, __nv_bfloat16* __restrict__ dl)
{
    int idx = blockIdx.x * 256 + threadIdx.x;
    if (idx >= CoPad * 256 * 9) return;
    int ci = idx & 255, t2 = idx >> 8;
    int co = t2 % CoPad, shift = t2 / CoPad;
    float v = 0.f;
    if (co < C1)            v = w1[((size_t)co * 256 + ci) * 9 + shift];
    else if (co < C1 + C2)  v = w2[((size_t)(co - C1) * 256 + ci) * 9 + shift];
    __nv_bfloat16 h = __float2bfloat16(v);
    dh[idx] = h;
    dl[idx] = __float2bfloat16(v - __bfloat162float(h));
}

// ================= HMMA implicit-GEMM 3x3 conv (pipelined A) =================
#define BROWS  464
#define BBYTES (BROWS * 128)            // 59392
#define BH_OFF 0
#define BL_OFF BBYTES                   // 59392
#define A_OFF  (2 * BBYTES)             // 118784; two 32KB A stages (hi 16K + lo 16K each)
#define SMTOT  (2 * BBYTES + 65536)     // 184320

__global__ void __launch_bounds__(512, 1) hmma_conv_kernel(
    const __nv_bfloat16* __restrict__ wh, const __nv_bfloat16* __restrict__ wl,
    const __nv_bfloat16* __restrict__ xh, const __nv_bfloat16* __restrict__ xl,
    const float* __restrict__ bias1, const float* __restrict__ bias2,
    float* __restrict__ out, int Cout1, int CoPad, int layout)
{
    extern __shared__ char smem[];
    const uint32_t sb = smem_u32(smem);
    const int tid = threadIdx.x, wid = tid >> 5, lane = tid & 31;
    const int warp_m = wid & 3, warp_n = wid >> 2;
    const int t = blockIdx.z, o0 = blockIdx.y << 8, co0 = blockIdx.x << 7;
    const int pmin = o0 + 2 * (o0 / 96);

    float C[2][8][4];
#pragma unroll
    for (int m = 0; m < 2; m++)
#pragma unroll
        for (int n = 0; n < 8; n++)
#pragma unroll
            for (int k = 0; k < 4; k++) C[m][n][k] = 0.f;

    const int kh_b = (lane >> 3) & 1;
    const int kh_a = lane >> 4;
    int prow[4];
#pragma unroll
    for (int j = 0; j < 4; j++) {
        int nl = warp_n * 64 + j * 16 + ((lane >> 4) << 3) + (lane & 7);
        int o = o0 + nl;
        prow[j] = o + 2 * (o / 96) + 99 - pmin;     // 99..360; +off in [0, 460)
    }
    int arow[2];
#pragma unroll
    for (int m = 0; m < 2; m++) arow[m] = warp_m * 32 + m * 16 + (lane & 15);

    // per-thread A-tile slots: idx = tid + i*512, i<2; r=idx>>3, c=idx&7
    const int ar0 = tid >> 3,          ac0 = tid & 7;
    const int ar1 = (tid + 512) >> 3,  ac1 = ac0;
    const uint32_t adof0 = ar0 * 128 + ((ac0 ^ (ar0 & 7)) << 4);
    const uint32_t adof1 = ar1 * 128 + ((ac1 ^ (ar1 & 7)) << 4);

    auto fetch_A = [&](int cs, uint4* regs) {
        const int chunk = cs / 9, shift = cs - chunk * 9;
        const size_t base0 = (((size_t)(shift * CoPad + co0 + ar0)) * 256 + chunk * 64) * 2;
        const size_t base1 = (((size_t)(shift * CoPad + co0 + ar1)) * 256 + chunk * 64) * 2;
        regs[0] = *(const uint4*)((const char*)wh + base0 + ac0 * 16);
        regs[1] = *(const uint4*)((const char*)wh + base1 + ac1 * 16);
        regs[2] = *(const uint4*)((const char*)wl + base0 + ac0 * 16);
        regs[3] = *(const uint4*)((const char*)wl + base1 + ac1 * 16);
    };
    auto store_A = [&](int cs, const uint4* regs) {
        char* st = smem + A_OFF + (cs & 1) * 32768;
        *(uint4*)(st + adof0)         = regs[0];
        *(uint4*)(st + adof1)         = regs[1];
        *(uint4*)(st + 16384 + adof0) = regs[2];
        *(uint4*)(st + 16384 + adof1) = regs[3];
    };
    auto load_B = [&](int chunk) {
        const int prem = PPIX_ - pmin;
        const size_t gb = (((size_t)t * PPIX_ + pmin) * 256 + chunk * 64) * 2;
#pragma unroll
        for (int i = 0; i < 8; i++) {
            int idx = tid + i * 512;
            if (idx < BROWS * 8) {
                int r = idx >> 3, c = idx & 7;
                uint32_t dof = r * 128 + ((c ^ (r & 7)) << 4);
                uint4 vh = make_uint4(0, 0, 0, 0), vl = make_uint4(0, 0, 0, 0);
                if (r < prem) {
                    vh = *(const uint4*)((const char*)xh + gb + (size_t)r * 512 + c * 16);
                    vl = *(const uint4*)((const char*)xl + gb + (size_t)r * 512 + c * 16);
                }
                *(uint4*)(smem + BH_OFF + dof) = vh;
                *(uint4*)(smem + BL_OFF + dof) = vl;
            }
        }
    };

    // prologue: B(0), A(0)
    load_B(0);
    {
        uint4 a0[4];
        fetch_A(0, a0);
        store_A(0, a0);
    }
    __syncthreads();

    for (int cs = 0; cs < 36; cs++) {
        const int shift = cs % 9;
        uint4 apre[4];
        if (cs + 1 < 36) fetch_A(cs + 1, apre);        // LDG overlapped with MMAs

        const uint32_t AH = sb + A_OFF + (cs & 1) * 32768;
        const uint32_t AL = AH + 16384;
        const int off = (shift / 3 - 1) * PW_ + (shift % 3 - 1);
#pragma unroll
        for (int ks = 0; ks < 4; ks++) {
            uint32_t a[2][4], b[4][4];
            // A hi
#pragma unroll
            for (int m = 0; m < 2; m++) {
                int c = ks * 2 + kh_a;
                ldsm4(a[m], AH + arow[m] * 128 + ((c ^ (arow[m] & 7)) << 4));
            }
            // B lo -> Ah*Bl
#pragma unroll
            for (int j = 0; j < 4; j++) {
                int r = prow[j] + off;
                int c = ks * 2 + kh_b;
                ldsm4(b[j], sb + BL_OFF + r * 128 + ((c ^ (r & 7)) << 4));
            }
#pragma unroll
            for (int m = 0; m < 2; m++)
#pragma unroll
                for (int n = 0; n < 8; n++)
                    mma16816(C[m][n], a[m], b[n >> 1][(n & 1) * 2], b[n >> 1][(n & 1) * 2 + 1]);
            // B hi -> Ah*Bh
#pragma unroll
            for (int j = 0; j < 4; j++) {
                int r = prow[j] + off;
                int c = ks * 2 + kh_b;
                ldsm4(b[j], sb + BH_OFF + r * 128 + ((c ^ (r & 7)) << 4));
            }
#pragma unroll
            for (int m = 0; m < 2; m++)
#pragma unroll
                for (int n = 0; n < 8; n++)
                    mma16816(C[m][n], a[m], b[n >> 1][(n & 1) * 2], b[n >> 1][(n & 1) * 2 + 1]);
            // A lo -> Al*Bh
#pragma unroll
            for (int m = 0; m < 2; m++) {
                int c = ks * 2 + kh_a;
                ldsm4(a[m], AL + arow[m] * 128 + ((c ^ (arow[m] & 7)) << 4));
            }
#pragma unroll
            for (int m = 0; m < 2; m++)
#pragma unroll
                for (int n = 0; n < 8; n++)
                    mma16816(C[m][n], a[m], b[n >> 1][(n & 1) * 2], b[n >> 1][(n & 1) * 2 + 1]);
        }

        if (cs + 1 < 36) store_A(cs + 1, apre);        // safe: buf consumed @ cs-1, synced
        __syncthreads();                               // A(cs+1)/B visible; next-iter safety
        if (shift == 8 && cs + 1 < 36) {
            load_B(cs / 9 + 1);
            __syncthreads();
        }
    }

    // epilogue
#pragma unroll
    for (int m = 0; m < 2; m++) {
        const int coA = co0 + warp_m * 32 + m * 16 + (lane >> 2);
#pragma unroll
        for (int n = 0; n < 8; n++) {
            const int px = o0 + warp_n * 64 + n * 8 + ((lane & 3) << 1);
#pragma unroll
            for (int half = 0; half < 2; half++) {
                const int co = coA + half * 8;
                const float v0 = C[m][n][half * 2 + 0];
                const float v1 = C[m][n][half * 2 + 1];
                if (layout == 0) {
                    const float bv = bias1[co];
                    float* op = out + ((size_t)t * Cout1 + co) * HW_ + px;
                    op[0] = v0 + bv; op[1] = v1 + bv;
                } else if (layout == 1) {
                    const float bv = bias1[co];
                    const int head = co >> 5, dh = co & 31;
                    float* op = g_value + (((size_t)(t * 8 + head) * HW_ + px) << 5) + dh;
                    op[0]  = v0 + bv;
                    op[32] = v1 + bv;
                } else {
                    if (co < 480) {
                        float bv; float* op;
                        if (co < 320) { bv = bias1[co];       op = g_off  + ((size_t)t * 320 + co)       * HW_ + px; }
                        else          { bv = bias2[co - 320]; op = g_attn + ((size_t)t * 160 + co - 320) * HW_ + px; }
                        op[0] = v0 + bv; op[1] = v1 + bv;
                    }
                }
            }
        }
    }
}

// ================= fused flow composition (single block) =================
__constant__ int c_flow_steps[9][3] = {
    // {base_slot, tgt_slot, dst_slot} as (i*5+j)
    {1,  7,  2},   // f02 = f01 + warp(f12, f01)
    {2, 13,  3},   // f03 = f02 + warp(f23, f02)
    {3, 19,  4},   // f04 = f03 + warp(f34, f03)
    {7, 13,  8},   // f13 = f12 + warp(f23, f12)
    {8, 19,  9},   // f14 = f13 + warp(f34, f13)
    {13, 19, 14},  // f24 = f23 + warp(f34, f23)
    {11, 5, 10},   // b20 = b21 + warp(b10, b21)
    {17, 11, 16},  // b31 = b32 + warp(b21, b32)
    {16, 5, 15},   // b30 = b31 + warp(b10, b31)
};

__global__ void __launch_bounds__(1024) flow_all_kernel(
    const float* __restrict__ ff, const float* __restrict__ fb)
{
    const int tid = threadIdx.x;
    // init
    for (int p = tid; p < HW_; p += 1024) {
#pragma unroll
        for (int i = 0; i < 4; i++)
#pragma unroll
            for (int j = 0; j < 5; j++) {
                g_adds[((i * 5 + j) * 2 + 0) * HW_ + p] = 0.f;
                g_adds[((i * 5 + j) * 2 + 1) * HW_ + p] = 0.f;
            }
#pragma unroll
        for (int k = 0; k < 4; k++) {
            g_adds[((k * 5 + (k + 1)) * 2 + 0) * HW_ + p] = ff[(k * 2 + 0) * HW_ + p];
            g_adds[((k * 5 + (k + 1)) * 2 + 1) * HW_ + p] = ff[(k * 2 + 1) * HW_ + p];
        }
#pragma unroll
        for (int k = 0; k < 3; k++) {
            g_adds[(((k + 1) * 5 + k) * 2 + 0) * HW_ + p] = fb[(k * 2 + 0) * HW_ + p];
            g_adds[(((k + 1) * 5 + k) * 2 + 1) * HW_ + p] = fb[(k * 2 + 1) * HW_ + p];
        }
    }
    __syncthreads();
    for (int step = 0; step < 9; step++) {
        const float* bptr = g_adds + c_flow_steps[step][0] * 2 * HW_;
        const float* tgt  = g_adds + c_flow_steps[step][1] * 2 * HW_;
        float*       dst  = g_adds + c_flow_steps[step][2] * 2 * HW_;
        for (int p = tid; p < HW_; p += 1024) {
            int y = p / W_, x = p - y * W_;
            float fx = bptr[p], fy = bptr[HW_ + p];
            float px = (float)x + fx, py = (float)y + fy;
            float x0f = floorf(px), y0f = floorf(py);
            int   x0 = (int)x0f, y0 = (int)y0f;
            float wx1 = px - x0f, wx0 = 1.f - wx1;
            float wy1 = py - y0f, wy0 = 1.f - wy1;
            float s0 = 0.f, s1 = 0.f;
            const int xs[4] = {x0, x0 + 1, x0, x0 + 1};
            const int ys[4] = {y0, y0, y0 + 1, y0 + 1};
            const float ws[4] = {wx0 * wy0, wx1 * wy0, wx0 * wy1, wx1 * wy1};
#pragma unroll
            for (int k = 0; k < 4; k++) {
                if ((unsigned)xs[k] < W_ && (unsigned)ys[k] < H_) {
                    int idx = ys[k] * W_ + xs[k];
                    s0 = fmaf(tgt[idx], ws[k], s0);
                    s1 = fmaf(tgt[HW_ + idx], ws[k], s1);
                }
            }
            dst[p]       = fx + s0;
            dst[HW_ + p] = fy + s1;
        }
        __syncthreads();
    }
}

// ================= deformable sampling =================
__global__ void __launch_bounds__(256) sample_kernel(const float* __restrict__ ref_pts)
{
    const int item = blockIdx.x * 8 + (threadIdx.x >> 5);
    const int lane = threadIdx.x & 31;
    const int head = item & 7;
    const int q    = item >> 3;
    const int t    = q / HW_;
    const int p    = q - t * HW_;
    const int ri   = (t == 4) ? 3 : t;

    const float* attn_base = g_attn + (size_t)t * 160 * HW_ + (size_t)head * 20 * HW_ + p;
    float lg[20];
    float mx = -1e30f;
#pragma unroll
    for (int i = 0; i < 20; i++) { lg[i] = attn_base[(size_t)i * HW_]; mx = fmaxf(mx, lg[i]); }
    float ssum = 0.f;
#pragma unroll
    for (int i = 0; i < 20; i++) { lg[i] = __expf(lg[i] - mx); ssum += lg[i]; }
    const float inv = 1.f / ssum;

    const float* off_base = g_off + (size_t)t * 320 * HW_ + p;
    float outv = 0.f;
#pragma unroll
    for (int l = 0; l < LVLS_; l++) {
        const float ax = g_adds[((ri * 5 + l) * 2 + 0) * HW_ + p];
        const float ay = g_adds[((ri * 5 + l) * 2 + 1) * HW_ + p];
        const float rx = ref_pts[((size_t)q * 5 + l) * 2 + 0];
        const float ry = ref_pts[((size_t)q * 5 + l) * 2 + 1];
        const float* vimg = g_value + ((size_t)(l * 8 + head) * HW_ << 5) + lane;
#pragma unroll
        for (int pt = 0; pt < PTS_; pt++) {
            const int ch = ((head * 5 + l) * 4 + pt) * 2;
            const float ox = off_base[(size_t)ch * HW_] + ax;
            const float oy = off_base[(size_t)(ch + 1) * HW_] + ay;
            const float px = fmaf(rx, (float)W_, ox) - 0.5f;
            const float py = fmaf(ry, (float)H_, oy) - 0.5f;
            const float x0f = floorf(px), y0f = floorf(py);
            const int   x0 = (int)x0f, y0 = (int)y0f;
            const float wx1 = px - x0f, wx0 = 1.f - wx1;
            const float wy1 = py - y0f, wy0 = 1.f - wy1;
            float s = 0.f;
            const bool vx0 = (unsigned)x0 < W_,       vx1 = (unsigned)(x0 + 1) < W_;
            const bool vy0 = (unsigned)y0 < H_,       vy1 = (unsigned)(y0 + 1) < H_;
            if (vy0) {
                const long long r0 = (long long)y0 * W_;
                if (vx0) s = fmaf(vimg[(r0 + x0) << 5],     wx0 * wy0, s);
                if (vx1) s = fmaf(vimg[(r0 + x0 + 1) << 5], wx1 * wy0, s);
            }
            if (vy1) {
                const long long r1 = (long long)(y0 + 1) * W_;
                if (vx0) s = fmaf(vimg[(r1 + x0) << 5],     wx0 * wy1, s);
                if (vx1) s = fmaf(vimg[(r1 + x0 + 1) << 5], wx1 * wy1, s);
            }
            outv = fmaf(s, lg[l * 4 + pt] * inv, outv);
        }
    }
    const int y = p / 96, x = p - y * 96;
    const size_t ob = ((size_t)t * PPIX_ + (size_t)(y + 1) * PW_ + x + 1) * 256 + (head << 5) + lane;
    __nv_bfloat16 h = __float2bfloat16(outv);
    g_xsh[ob] = h;
    g_xsl[ob] = __float2bfloat16(outv - __bfloat162float(h));
}

// ================= launch =================
extern "C" void kernel_launch(void* const* d_in, const int* in_sizes, int n_in,
                              void* d_out, int out_size)
{
    (void)in_sizes; (void)n_in; (void)out_size;
    const float* query         = (const float*)d_in[0];
    const float* input_flatten = (const float*)d_in[1];
    const float* ref_pts       = (const float*)d_in[2];
    const float* ff     = (const float*)d_in[6];
    const float* fb     = (const float*)d_in[7];
    const float* w_off  = (const float*)d_in[8];
    const float* b_off  = (const float*)d_in[9];
    const float* w_attn = (const float*)d_in[10];
    const float* b_attn = (const float*)d_in[11];
    const float* w_val  = (const float*)d_in[12];
    const float* b_val  = (const float*)d_in[13];
    const float* w_out  = (const float*)d_in[14];
    const float* b_out  = (const float*)d_in[15];
    float* out = (float*)d_out;

    cudaFuncSetAttribute(hmma_conv_kernel, cudaFuncAttributeMaxDynamicSharedMemorySize, SMTOT);

    __nv_bfloat16 *xfh, *xfl, *xqh, *xql, *xsh, *xsl;
    __nv_bfloat16 *wvh, *wvl, *wph, *wpl, *wuh, *wul;
    cudaGetSymbolAddress((void**)&xfh, g_xfh); cudaGetSymbolAddress((void**)&xfl, g_xfl);
    cudaGetSymbolAddress((void**)&xqh, g_xqh); cudaGetSymbolAddress((void**)&xql, g_xql);
    cudaGetSymbolAddress((void**)&xsh, g_xsh); cudaGetSymbolAddress((void**)&xsl, g_xsl);
    cudaGetSymbolAddress((void**)&wvh, g_wvh); cudaGetSymbolAddress((void**)&wvl, g_wvl);
    cudaGetSymbolAddress((void**)&wph, g_wph); cudaGetSymbolAddress((void**)&wpl, g_wpl);
    cudaGetSymbolAddress((void**)&wuh, g_wuh); cudaGetSymbolAddress((void**)&wul, g_wul);

    // ---- preps (ordered so launch index 5 = value conv, for ncu -s 5) ----
    zero_border_kernel<<<(T_ * PPIX_ * 32 + 255) / 256, 256>>>();          // 0
    prep_x_kernel<<<dim3(64, 5), 128>>>(input_flatten, xfh, xfl);          // 1
    prep_x_kernel<<<dim3(64, 5), 128>>>(query, xqh, xql);                  // 2
    prep_w_kernel<<<(256 * 256 * 9 + 255) / 256, 256>>>(w_val, 256, nullptr, 0, 256, wvh, wvl);      // 3
    prep_w_kernel<<<(512 * 256 * 9 + 255) / 256, 256>>>(w_off, 320, w_attn, 160, 512, wph, wpl);     // 4

    // ---- value conv (launch 5: profiled) ----
    hmma_conv_kernel<<<dim3(2, 24, 5), 512, SMTOT>>>(wvh, wvl, xfh, xfl, b_val, nullptr, nullptr, 256, 256, 1);

    // ---- flow composition (fused, single block) ----
    flow_all_kernel<<<1, 1024>>>(ff, fb);

    // ---- fused off+attn conv ----
    hmma_conv_kernel<<<dim3(4, 24, 5), 512, SMTOT>>>(wph, wpl, xqh, xql, b_off, b_attn, nullptr, 320, 512, 2);

    // ---- deformable attention sampling ----
    sample_kernel<<<(T_ * HW_ * HEADS_) / 8, 256>>>(ref_pts);

    // ---- output projection ----
    prep_w_kernel<<<(256 * 256 * 9 + 255) / 256, 256>>>(w_out, 256, nullptr, 0, 256, wuh, wul);
    hmma_conv_kernel<<<dim3(2, 24, 5), 512, SMTOT>>>(wuh, wul, xsh, xsl, b_out, nullptr, out, 256, 256, 0);
}

// round 7
// speedup vs baseline: 1.2037x; 1.2037x over previous
#include <cuda_runtime.h>
#include <cuda_fp16.h>
#include <cstdint>
#include <math.h>

#define T_ 5
#define H_ 64
#define W_ 96
#define HW_ (H_ * W_)
#define HEADS_ 8
#define LVLS_ 5
#define PTS_ 4
#define NPIX_ (T_ * HW_)
#define PW_ (W_ + 2)            // 98
#define PH_ (H_ + 2)            // 66
#define PPIX_ (PW_ * PH_)       // 6468

// ================= helpers =================
__device__ __forceinline__ uint32_t smem_u32(const void* p) {
    uint32_t a;
    asm("{ .reg .u64 t; cvta.to.shared.u64 t, %1; cvt.u32.u64 %0, t; }" : "=r"(a) : "l"(p));
    return a;
}
__device__ __forceinline__ void ldsm4(uint32_t* r, uint32_t addr) {
    asm volatile("ldmatrix.sync.aligned.m8n8.x4.shared.b16 {%0,%1,%2,%3}, [%4];"
        : "=r"(r[0]), "=r"(r[1]), "=r"(r[2]), "=r"(r[3]) : "r"(addr));
}
__device__ __forceinline__ void mma16816(float* c, const uint32_t* a, uint32_t b0, uint32_t b1) {
    asm volatile(
        "mma.sync.aligned.m16n8k16.row.col.f32.f16.f16.f32 "
        "{%0,%1,%2,%3}, {%4,%5,%6,%7}, {%8,%9}, {%0,%1,%2,%3};"
        : "+f"(c[0]), "+f"(c[1]), "+f"(c[2]), "+f"(c[3])
        : "r"(a[0]), "r"(a[1]), "r"(a[2]), "r"(a[3]), "r"(b0), "r"(b1));
}

// ================= scratch =================
// padded pixel-major fp16 hi/lo inputs: [t][ppix][256]
__device__ __align__(16) __half g_xfh[(size_t)T_ * PPIX_ * 256], g_xfl[(size_t)T_ * PPIX_ * 256];
__device__ __align__(16) __half g_xqh[(size_t)T_ * PPIX_ * 256], g_xql[(size_t)T_ * PPIX_ * 256];
__device__ __align__(16) __half g_xsh[(size_t)T_ * PPIX_ * 256], g_xsl[(size_t)T_ * PPIX_ * 256];
// weights [shift][CoPad][256] fp16 (single precision level)
__device__ __align__(16) __half g_wv[9 * 256 * 256];
__device__ __align__(16) __half g_wp[9 * 512 * 256];   // off+attn fused
__device__ __align__(16) __half g_wu[9 * 256 * 256];
__device__ __align__(16) __half g_value[(size_t)T_ * HEADS_ * HW_ * 32];   // fp16 [t][head][pix][dh]
__device__ float g_off  [(size_t)T_ * 320 * HW_];
__device__ float g_attn [(size_t)T_ * 160 * HW_];
__device__ float g_adds [(size_t)4 * 5 * 2 * HW_];

// ================= border zeroing of padded buffers (ALL 256 channels) =================
__global__ void zero_border_kernel()
{
    int idx = blockIdx.x * 256 + threadIdx.x;          // [t][ppix][c32]
    if (idx >= T_ * PPIX_ * 32) return;
    int c32 = idx & 31;
    int pp  = (idx >> 5) % PPIX_;
    int t   = idx / (PPIX_ * 32);
    int py = pp / PW_, px = pp - py * PW_;
    if (py == 0 || py == PH_ - 1 || px == 0 || px == PW_ - 1) {
        size_t o = ((size_t)t * PPIX_ + pp) * 256 + c32 * 8;   // half elements
        uint4 z = make_uint4(0, 0, 0, 0);
        *(uint4*)((char*)g_xfh + o * 2) = z; *(uint4*)((char*)g_xfl + o * 2) = z;
        *(uint4*)((char*)g_xqh + o * 2) = z; *(uint4*)((char*)g_xql + o * 2) = z;
        *(uint4*)((char*)g_xsh + o * 2) = z; *(uint4*)((char*)g_xsl + o * 2) = z;
    }
}

// ================= input transpose + fp16 hi/lo split (interior) =================
__global__ void __launch_bounds__(128) prep_x_kernel(
    const float* __restrict__ src, __half* __restrict__ dh, __half* __restrict__ dl)
{
    const int y = blockIdx.x, t = blockIdx.y, tid = threadIdx.x;
    __shared__ float s[64][97];
    for (int cib = 0; cib < 4; cib++) {
        __syncthreads();
        for (int i = tid; i < 64 * 96; i += 128) {
            int r = i / 96, c = i - r * 96;
            s[r][c] = src[((size_t)(t * 256 + cib * 64 + r)) * HW_ + y * 96 + c];
        }
        __syncthreads();
        if (tid < 96) {
            size_t ob = ((size_t)t * PPIX_ + (size_t)(y + 1) * PW_ + tid + 1) * 256 + cib * 64;
#pragma unroll 8
            for (int ci = 0; ci < 64; ci++) {
                float v = s[ci][tid];
                __half h = __float2half(v);
                dh[ob + ci] = h;
                dl[ob + ci] = __float2half(v - __half2float(h));
            }
        }
    }
}

// weights [co][256][3][3] fp32 (x2 sources) -> [shift][CoPad][256] fp16
__global__ void prep_w_kernel(const float* __restrict__ w1, int C1,
                              const float* __restrict__ w2, int C2, int CoPad,
                              __half* __restrict__ dw)
{
    int idx = blockIdx.x * 256 + threadIdx.x;
    if (idx >= CoPad * 256 * 9) return;
    int ci = idx & 255, t2 = idx >> 8;
    int co = t2 % CoPad, shift = t2 / CoPad;
    float v = 0.f;
    if (co < C1)            v = w1[((size_t)co * 256 + ci) * 9 + shift];
    else if (co < C1 + C2)  v = w2[((size_t)(co - C1) * 256 + ci) * 9 + shift];
    dw[idx] = __float2half(v);
}

// ================= HMMA implicit-GEMM 3x3 conv (fp16, 2-term) =================
// CTA: 128 co x 256 pix, 512 threads (16 warps: warp_m = wid&3, warp_n = wid>>2).
// C = W*Xh + W*Xl. B tile: 464 padded rows x 128B (hi+lo). A: single fp16 tile, 2 stages.
#define BROWS  464
#define BBYTES (BROWS * 128)            // 59392
#define BH_OFF 0
#define BL_OFF BBYTES                   // 59392
#define A_OFF  (2 * BBYTES)             // 118784; two 16KB A stages
#define SMTOT  (2 * BBYTES + 32768)     // 151552

__global__ void __launch_bounds__(512, 1) hmma_conv_kernel(
    const __half* __restrict__ wgt,
    const __half* __restrict__ xh, const __half* __restrict__ xl,
    const float* __restrict__ bias1, const float* __restrict__ bias2,
    float* __restrict__ out, int Cout1, int CoPad, int layout)
{
    extern __shared__ char smem[];
    const uint32_t sb = smem_u32(smem);
    const int tid = threadIdx.x, wid = tid >> 5, lane = tid & 31;
    const int warp_m = wid & 3, warp_n = wid >> 2;
    const int t = blockIdx.z, o0 = blockIdx.y << 8, co0 = blockIdx.x << 7;
    const int pmin = o0 + 2 * (o0 / 96);

    float C[2][8][4];
#pragma unroll
    for (int m = 0; m < 2; m++)
#pragma unroll
        for (int n = 0; n < 8; n++)
#pragma unroll
            for (int k = 0; k < 4; k++) C[m][n][k] = 0.f;

    const int kh_b = (lane >> 3) & 1;
    const int kh_a = lane >> 4;
    int prow[4];
#pragma unroll
    for (int j = 0; j < 4; j++) {
        int nl = warp_n * 64 + j * 16 + ((lane >> 4) << 3) + (lane & 7);
        int o = o0 + nl;
        prow[j] = o + 2 * (o / 96) + 99 - pmin;     // 99..360; +off in [0, 460)
    }
    int arow[2];
#pragma unroll
    for (int m = 0; m < 2; m++) arow[m] = warp_m * 32 + m * 16 + (lane & 15);

    const int ar0 = tid >> 3,          ac0 = tid & 7;
    const int ar1 = (tid + 512) >> 3;
    const uint32_t adof0 = ar0 * 128 + ((ac0 ^ (ar0 & 7)) << 4);
    const uint32_t adof1 = ar1 * 128 + ((ac0 ^ (ar1 & 7)) << 4);

    auto fetch_A = [&](int cs, uint4* regs) {
        const int chunk = cs / 9, shift = cs - chunk * 9;
        const size_t base0 = (((size_t)(shift * CoPad + co0 + ar0)) * 256 + chunk * 64) * 2;
        const size_t base1 = (((size_t)(shift * CoPad + co0 + ar1)) * 256 + chunk * 64) * 2;
        regs[0] = *(const uint4*)((const char*)wgt + base0 + ac0 * 16);
        regs[1] = *(const uint4*)((const char*)wgt + base1 + ac0 * 16);
    };
    auto store_A = [&](int cs, const uint4* regs) {
        char* st = smem + A_OFF + (cs & 1) * 16384;
        *(uint4*)(st + adof0) = regs[0];
        *(uint4*)(st + adof1) = regs[1];
    };
    auto load_B = [&](int chunk) {
        const int prem = PPIX_ - pmin;
        const size_t gb = (((size_t)t * PPIX_ + pmin) * 256 + chunk * 64) * 2;
#pragma unroll
        for (int i = 0; i < 8; i++) {
            int idx = tid + i * 512;
            if (idx < BROWS * 8) {
                int r = idx >> 3, c = idx & 7;
                uint32_t dof = r * 128 + ((c ^ (r & 7)) << 4);
                uint4 vh = make_uint4(0, 0, 0, 0), vl = make_uint4(0, 0, 0, 0);
                if (r < prem) {
                    vh = *(const uint4*)((const char*)xh + gb + (size_t)r * 512 + c * 16);
                    vl = *(const uint4*)((const char*)xl + gb + (size_t)r * 512 + c * 16);
                }
                *(uint4*)(smem + BH_OFF + dof) = vh;
                *(uint4*)(smem + BL_OFF + dof) = vl;
            }
        }
    };

    // prologue: B(0), A(0)
    load_B(0);
    {
        uint4 a0[2];
        fetch_A(0, a0);
        store_A(0, a0);
    }
    __syncthreads();

    for (int cs = 0; cs < 36; cs++) {
        const int shift = cs % 9;
        uint4 apre[2];
        if (cs + 1 < 36) fetch_A(cs + 1, apre);        // LDG overlapped with MMAs

        const uint32_t AS = sb + A_OFF + (cs & 1) * 16384;
        const int off = (shift / 3 - 1) * PW_ + (shift % 3 - 1);
#pragma unroll
        for (int ks = 0; ks < 4; ks++) {
            uint32_t a[2][4], b[4][4];
#pragma unroll
            for (int m = 0; m < 2; m++) {
                int c = ks * 2 + kh_a;
                ldsm4(a[m], AS + arow[m] * 128 + ((c ^ (arow[m] & 7)) << 4));
            }
            // W * Xl
#pragma unroll
            for (int j = 0; j < 4; j++) {
                int r = prow[j] + off;
                int c = ks * 2 + kh_b;
                ldsm4(b[j], sb + BL_OFF + r * 128 + ((c ^ (r & 7)) << 4));
            }
#pragma unroll
            for (int m = 0; m < 2; m++)
#pragma unroll
                for (int n = 0; n < 8; n++)
                    mma16816(C[m][n], a[m], b[n >> 1][(n & 1) * 2], b[n >> 1][(n & 1) * 2 + 1]);
            // W * Xh
#pragma unroll
            for (int j = 0; j < 4; j++) {
                int r = prow[j] + off;
                int c = ks * 2 + kh_b;
                ldsm4(b[j], sb + BH_OFF + r * 128 + ((c ^ (r & 7)) << 4));
            }
#pragma unroll
            for (int m = 0; m < 2; m++)
#pragma unroll
                for (int n = 0; n < 8; n++)
                    mma16816(C[m][n], a[m], b[n >> 1][(n & 1) * 2], b[n >> 1][(n & 1) * 2 + 1]);
        }

        if (cs + 1 < 36) store_A(cs + 1, apre);
        __syncthreads();
        if (shift == 8 && cs + 1 < 36) {
            load_B(cs / 9 + 1);
            __syncthreads();
        }
    }

    // epilogue
#pragma unroll
    for (int m = 0; m < 2; m++) {
        const int coA = co0 + warp_m * 32 + m * 16 + (lane >> 2);
#pragma unroll
        for (int n = 0; n < 8; n++) {
            const int px = o0 + warp_n * 64 + n * 8 + ((lane & 3) << 1);
#pragma unroll
            for (int half = 0; half < 2; half++) {
                const int co = coA + half * 8;
                const float v0 = C[m][n][half * 2 + 0];
                const float v1 = C[m][n][half * 2 + 1];
                if (layout == 0) {
                    const float bv = bias1[co];
                    float* op = out + ((size_t)t * Cout1 + co) * HW_ + px;
                    op[0] = v0 + bv; op[1] = v1 + bv;
                } else if (layout == 1) {
                    const float bv = bias1[co];
                    const int head = co >> 5, dh = co & 31;
                    __half* op = g_value + (((size_t)(t * 8 + head) * HW_ + px) << 5) + dh;
                    op[0]  = __float2half(v0 + bv);
                    op[32] = __float2half(v1 + bv);
                } else {
                    if (co < 480) {
                        float bv; float* op;
                        if (co < 320) { bv = bias1[co];       op = g_off  + ((size_t)t * 320 + co)       * HW_ + px; }
                        else          { bv = bias2[co - 320]; op = g_attn + ((size_t)t * 160 + co - 320) * HW_ + px; }
                        op[0] = v0 + bv; op[1] = v1 + bv;
                    }
                }
            }
        }
    }
}

// ================= fused flow composition (single block) =================
__constant__ int c_flow_steps[9][3] = {
    {1,  7,  2},   // f02
    {2, 13,  3},   // f03
    {3, 19,  4},   // f04
    {7, 13,  8},   // f13
    {8, 19,  9},   // f14
    {13, 19, 14},  // f24
    {11, 5, 10},   // b20
    {17, 11, 16},  // b31
    {16, 5, 15},   // b30
};

__global__ void __launch_bounds__(1024) flow_all_kernel(
    const float* __restrict__ ff, const float* __restrict__ fb)
{
    const int tid = threadIdx.x;
    for (int p = tid; p < HW_; p += 1024) {
#pragma unroll
        for (int i = 0; i < 4; i++)
#pragma unroll
            for (int j = 0; j < 5; j++) {
                g_adds[((i * 5 + j) * 2 + 0) * HW_ + p] = 0.f;
                g_adds[((i * 5 + j) * 2 + 1) * HW_ + p] = 0.f;
            }
#pragma unroll
        for (int k = 0; k < 4; k++) {
            g_adds[((k * 5 + (k + 1)) * 2 + 0) * HW_ + p] = ff[(k * 2 + 0) * HW_ + p];
            g_adds[((k * 5 + (k + 1)) * 2 + 1) * HW_ + p] = ff[(k * 2 + 1) * HW_ + p];
        }
#pragma unroll
        for (int k = 0; k < 3; k++) {
            g_adds[(((k + 1) * 5 + k) * 2 + 0) * HW_ + p] = fb[(k * 2 + 0) * HW_ + p];
            g_adds[(((k + 1) * 5 + k) * 2 + 1) * HW_ + p] = fb[(k * 2 + 1) * HW_ + p];
        }
    }
    __syncthreads();
    for (int step = 0; step < 9; step++) {
        const float* bptr = g_adds + c_flow_steps[step][0] * 2 * HW_;
        const float* tgt  = g_adds + c_flow_steps[step][1] * 2 * HW_;
        float*       dst  = g_adds + c_flow_steps[step][2] * 2 * HW_;
        for (int p = tid; p < HW_; p += 1024) {
            int y = p / W_, x = p - y * W_;
            float fx = bptr[p], fy = bptr[HW_ + p];
            float px = (float)x + fx, py = (float)y + fy;
            float x0f = floorf(px), y0f = floorf(py);
            int   x0 = (int)x0f, y0 = (int)y0f;
            float wx1 = px - x0f, wx0 = 1.f - wx1;
            float wy1 = py - y0f, wy0 = 1.f - wy1;
            float s0 = 0.f, s1 = 0.f;
            const int xs[4] = {x0, x0 + 1, x0, x0 + 1};
            const int ys[4] = {y0, y0, y0 + 1, y0 + 1};
            const float ws[4] = {wx0 * wy0, wx1 * wy0, wx0 * wy1, wx1 * wy1};
#pragma unroll
            for (int k = 0; k < 4; k++) {
                if ((unsigned)xs[k] < W_ && (unsigned)ys[k] < H_) {
                    int idx = ys[k] * W_ + xs[k];
                    s0 = fmaf(tgt[idx], ws[k], s0);
                    s1 = fmaf(tgt[HW_ + idx], ws[k], s1);
                }
            }
            dst[p]       = fx + s0;
            dst[HW_ + p] = fy + s1;
        }
        __syncthreads();
    }
}

// ================= deformable sampling (fp16 value cache) =================
__global__ void __launch_bounds__(256) sample_kernel(const float* __restrict__ ref_pts)
{
    const int item = blockIdx.x * 8 + (threadIdx.x >> 5);
    const int lane = threadIdx.x & 31;
    const int head = item & 7;
    const int q    = item >> 3;
    const int t    = q / HW_;
    const int p    = q - t * HW_;
    const int ri   = (t == 4) ? 3 : t;

    const float* attn_base = g_attn + (size_t)t * 160 * HW_ + (size_t)head * 20 * HW_ + p;
    float lg[20];
    float mx = -1e30f;
#pragma unroll
    for (int i = 0; i < 20; i++) { lg[i] = attn_base[(size_t)i * HW_]; mx = fmaxf(mx, lg[i]); }
    float ssum = 0.f;
#pragma unroll
    for (int i = 0; i < 20; i++) { lg[i] = __expf(lg[i] - mx); ssum += lg[i]; }
    const float inv = 1.f / ssum;

    const float* off_base = g_off + (size_t)t * 320 * HW_ + p;
    float outv = 0.f;
#pragma unroll
    for (int l = 0; l < LVLS_; l++) {
        const float ax = g_adds[((ri * 5 + l) * 2 + 0) * HW_ + p];
        const float ay = g_adds[((ri * 5 + l) * 2 + 1) * HW_ + p];
        const float rx = ref_pts[((size_t)q * 5 + l) * 2 + 0];
        const float ry = ref_pts[((size_t)q * 5 + l) * 2 + 1];
        const __half* vimg = g_value + ((size_t)(l * 8 + head) * HW_ << 5) + lane;
#pragma unroll
        for (int pt = 0; pt < PTS_; pt++) {
            const int ch = ((head * 5 + l) * 4 + pt) * 2;
            const float ox = off_base[(size_t)ch * HW_] + ax;
            const float oy = off_base[(size_t)(ch + 1) * HW_] + ay;
            const float px = fmaf(rx, (float)W_, ox) - 0.5f;
            const float py = fmaf(ry, (float)H_, oy) - 0.5f;
            const float x0f = floorf(px), y0f = floorf(py);
            const int   x0 = (int)x0f, y0 = (int)y0f;
            const float wx1 = px - x0f, wx0 = 1.f - wx1;
            const float wy1 = py - y0f, wy0 = 1.f - wy1;
            float s = 0.f;
            const bool vx0 = (unsigned)x0 < W_,       vx1 = (unsigned)(x0 + 1) < W_;
            const bool vy0 = (unsigned)y0 < H_,       vy1 = (unsigned)(y0 + 1) < H_;
            if (vy0) {
                const long long r0 = (long long)y0 * W_;
                if (vx0) s = fmaf(__half2float(vimg[(r0 + x0) << 5]),     wx0 * wy0, s);
                if (vx1) s = fmaf(__half2float(vimg[(r0 + x0 + 1) << 5]), wx1 * wy0, s);
            }
            if (vy1) {
                const long long r1 = (long long)(y0 + 1) * W_;
                if (vx0) s = fmaf(__half2float(vimg[(r1 + x0) << 5]),     wx0 * wy1, s);
                if (vx1) s = fmaf(__half2float(vimg[(r1 + x0 + 1) << 5]), wx1 * wy1, s);
            }
            outv = fmaf(s, lg[l * 4 + pt] * inv, outv);
        }
    }
    const int y = p / 96, x = p - y * 96;
    const size_t ob = ((size_t)t * PPIX_ + (size_t)(y + 1) * PW_ + x + 1) * 256 + (head << 5) + lane;
    __half h = __float2half(outv);
    g_xsh[ob] = h;
    g_xsl[ob] = __float2half(outv - __half2float(h));
}

// ================= launch =================
extern "C" void kernel_launch(void* const* d_in, const int* in_sizes, int n_in,
                              void* d_out, int out_size)
{
    (void)in_sizes; (void)n_in; (void)out_size;
    const float* query         = (const float*)d_in[0];
    const float* input_flatten = (const float*)d_in[1];
    const float* ref_pts       = (const float*)d_in[2];
    const float* ff     = (const float*)d_in[6];
    const float* fb     = (const float*)d_in[7];
    const float* w_off  = (const float*)d_in[8];
    const float* b_off  = (const float*)d_in[9];
    const float* w_attn = (const float*)d_in[10];
    const float* b_attn = (const float*)d_in[11];
    const float* w_val  = (const float*)d_in[12];
    const float* b_val  = (const float*)d_in[13];
    const float* w_out  = (const float*)d_in[14];
    const float* b_out  = (const float*)d_in[15];
    float* out = (float*)d_out;

    cudaFuncSetAttribute(hmma_conv_kernel, cudaFuncAttributeMaxDynamicSharedMemorySize, SMTOT);

    __half *xfh, *xfl, *xqh, *xql, *xsh, *xsl, *wv, *wp, *wu;
    cudaGetSymbolAddress((void**)&xfh, g_xfh); cudaGetSymbolAddress((void**)&xfl, g_xfl);
    cudaGetSymbolAddress((void**)&xqh, g_xqh); cudaGetSymbolAddress((void**)&xql, g_xql);
    cudaGetSymbolAddress((void**)&xsh, g_xsh); cudaGetSymbolAddress((void**)&xsl, g_xsl);
    cudaGetSymbolAddress((void**)&wv, g_wv);
    cudaGetSymbolAddress((void**)&wp, g_wp);
    cudaGetSymbolAddress((void**)&wu, g_wu);

    // ---- preps ----
    zero_border_kernel<<<(T_ * PPIX_ * 32 + 255) / 256, 256>>>();
    prep_x_kernel<<<dim3(64, 5), 128>>>(input_flatten, xfh, xfl);
    prep_x_kernel<<<dim3(64, 5), 128>>>(query, xqh, xql);
    prep_w_kernel<<<(256 * 256 * 9 + 255) / 256, 256>>>(w_val, 256, nullptr, 0, 256, wv);
    prep_w_kernel<<<(512 * 256 * 9 + 255) / 256, 256>>>(w_off, 320, w_attn, 160, 512, wp);
    prep_w_kernel<<<(256 * 256 * 9 + 255) / 256, 256>>>(w_out, 256, nullptr, 0, 256, wu);

    // ---- flow composition (fused, single block) ----
    flow_all_kernel<<<1, 1024>>>(ff, fb);

    // ---- convs + sampling ----
    hmma_conv_kernel<<<dim3(2, 24, 5), 512, SMTOT>>>(wv, xfh, xfl, b_val, nullptr, nullptr, 256, 256, 1);
    hmma_conv_kernel<<<dim3(4, 24, 5), 512, SMTOT>>>(wp, xqh, xql, b_off, b_attn, nullptr, 320, 512, 2);
    sample_kernel<<<(T_ * HW_ * HEADS_) / 8, 256>>>(ref_pts);
    hmma_conv_kernel<<<dim3(2, 24, 5), 512, SMTOT>>>(wu, xsh, xsl, b_out, nullptr, out, 256, 256, 0);
}

// round 9
// speedup vs baseline: 1.2797x; 1.0631x over previous
#include <cuda_runtime.h>
#include <cuda_fp16.h>
#include <cstdint>
#include <math.h>

#define T_ 5
#define H_ 64
#define W_ 96
#define HW_ (H_ * W_)
#define HEADS_ 8
#define LVLS_ 5
#define PTS_ 4
#define NPIX_ (T_ * HW_)
#define PW_ (W_ + 2)            // 98
#define PH_ (H_ + 2)            // 66
#define PPIX_ (PW_ * PH_)       // 6468

// ================= helpers =================
__device__ __forceinline__ uint32_t smem_u32(const void* p) {
    uint32_t a;
    asm("{ .reg .u64 t; cvta.to.shared.u64 t, %1; cvt.u32.u64 %0, t; }" : "=r"(a) : "l"(p));
    return a;
}
__device__ __forceinline__ void ldsm4(uint32_t* r, uint32_t addr) {
    asm volatile("ldmatrix.sync.aligned.m8n8.x4.shared.b16 {%0,%1,%2,%3}, [%4];"
        : "=r"(r[0]), "=r"(r[1]), "=r"(r[2]), "=r"(r[3]) : "r"(addr));
}
__device__ __forceinline__ void mma16816(float* c, const uint32_t* a, uint32_t b0, uint32_t b1) {
    asm volatile(
        "mma.sync.aligned.m16n8k16.row.col.f32.f16.f16.f32 "
        "{%0,%1,%2,%3}, {%4,%5,%6,%7}, {%8,%9}, {%0,%1,%2,%3};"
        : "+f"(c[0]), "+f"(c[1]), "+f"(c[2]), "+f"(c[3])
        : "r"(a[0]), "r"(a[1]), "r"(a[2]), "r"(a[3]), "r"(b0), "r"(b1));
}

// ================= scratch =================
__device__ __align__(16) __half g_xfh[(size_t)T_ * PPIX_ * 256], g_xfl[(size_t)T_ * PPIX_ * 256];
__device__ __align__(16) __half g_xqh[(size_t)T_ * PPIX_ * 256], g_xql[(size_t)T_ * PPIX_ * 256];
__device__ __align__(16) __half g_xsh[(size_t)T_ * PPIX_ * 256], g_xsl[(size_t)T_ * PPIX_ * 256];
__device__ __align__(16) __half g_wv[9 * 256 * 256];
__device__ __align__(16) __half g_wp[9 * 512 * 256];   // off+attn fused
__device__ __align__(16) __half g_wu[9 * 256 * 256];
__device__ __align__(16) __half g_value[(size_t)T_ * HEADS_ * HW_ * 32];   // [t][head][pix][dh]
__device__ float g_off  [(size_t)T_ * 320 * HW_];
__device__ float g_attn [(size_t)T_ * 160 * HW_];
__device__ float g_adds [(size_t)4 * 5 * 2 * HW_];

// ================= border zeroing =================
__global__ void zero_border_kernel()
{
    int idx = blockIdx.x * 256 + threadIdx.x;          // [t][ppix][c32]
    if (idx >= T_ * PPIX_ * 32) return;
    int c32 = idx & 31;
    int pp  = (idx >> 5) % PPIX_;
    int t   = idx / (PPIX_ * 32);
    int py = pp / PW_, px = pp - py * PW_;
    if (py == 0 || py == PH_ - 1 || px == 0 || px == PW_ - 1) {
        size_t o = ((size_t)t * PPIX_ + pp) * 256 + c32 * 8;
        uint4 z = make_uint4(0, 0, 0, 0);
        *(uint4*)((char*)g_xfh + o * 2) = z; *(uint4*)((char*)g_xfl + o * 2) = z;
        *(uint4*)((char*)g_xqh + o * 2) = z; *(uint4*)((char*)g_xql + o * 2) = z;
        *(uint4*)((char*)g_xsh + o * 2) = z; *(uint4*)((char*)g_xsl + o * 2) = z;
    }
}

// ================= input transpose + fp16 hi/lo split =================
__global__ void __launch_bounds__(128) prep_x_kernel(
    const float* __restrict__ src, __half* __restrict__ dh, __half* __restrict__ dl)
{
    const int y = blockIdx.x, t = blockIdx.y, tid = threadIdx.x;
    __shared__ float s[64][97];
    for (int cib = 0; cib < 4; cib++) {
        __syncthreads();
        for (int i = tid; i < 64 * 96; i += 128) {
            int r = i / 96, c = i - r * 96;
            s[r][c] = src[((size_t)(t * 256 + cib * 64 + r)) * HW_ + y * 96 + c];
        }
        __syncthreads();
        if (tid < 96) {
            size_t ob = ((size_t)t * PPIX_ + (size_t)(y + 1) * PW_ + tid + 1) * 256 + cib * 64;
#pragma unroll 8
            for (int ci = 0; ci < 64; ci++) {
                float v = s[ci][tid];
                __half h = __float2half(v);
                dh[ob + ci] = h;
                dl[ob + ci] = __float2half(v - __half2float(h));
            }
        }
    }
}

// weights -> [shift][CoPad][256] fp16
__global__ void prep_w_kernel(const float* __restrict__ w1, int C1,
                              const float* __restrict__ w2, int C2, int CoPad,
                              __half* __restrict__ dw)
{
    int idx = blockIdx.x * 256 + threadIdx.x;
    if (idx >= CoPad * 256 * 9) return;
    int ci = idx & 255, t2 = idx >> 8;
    int co = t2 % CoPad, shift = t2 / CoPad;
    float v = 0.f;
    if (co < C1)            v = w1[((size_t)co * 256 + ci) * 9 + shift];
    else if (co < C1 + C2)  v = w2[((size_t)(co - C1) * 256 + ci) * 9 + shift];
    dw[idx] = __float2half(v);
}

// ================= HMMA implicit-GEMM 3x3 conv (128co x 128pix, occ 2) =================
#define BROWS  330
#define BBYTES (BROWS * 128)            // 42240
#define BH_OFF 0
#define BL_OFF BBYTES                   // 42240
#define A_OFF  (2 * BBYTES)             // 84480 (128B aligned)
#define SMTOT  (2 * BBYTES + 16384)     // 100864

__device__ __forceinline__ void conv_body(char* smem,
    const __half* __restrict__ wgt,
    const __half* __restrict__ xh, const __half* __restrict__ xl,
    const float* __restrict__ bias1, const float* __restrict__ bias2,
    float* __restrict__ out, int Cout1, int CoPad, int layout, int co0)
{
    const uint32_t sb = smem_u32(smem);
    const int tid = threadIdx.x, wid = tid >> 5, lane = tid & 31;
    const int warp_m = wid & 3, warp_n = wid >> 2;           // 4 co-warps x 2 pix-warps
    const int t = blockIdx.z, o0 = blockIdx.y << 7;          // 128-pixel tile
    const int pmin = o0 + 2 * (o0 / 96);

    float C[2][8][4];
#pragma unroll
    for (int m = 0; m < 2; m++)
#pragma unroll
        for (int n = 0; n < 8; n++)
#pragma unroll
            for (int k = 0; k < 4; k++) C[m][n][k] = 0.f;

    const int kh_b = (lane >> 3) & 1;
    const int kh_a = lane >> 4;
    int prow[4];
#pragma unroll
    for (int j = 0; j < 4; j++) {
        int nl = warp_n * 64 + j * 16 + ((lane >> 4) << 3) + (lane & 7);
        int o = o0 + nl;
        prow[j] = o + 2 * (o / 96) + 99 - pmin;     // in [99, 229); +off stays in [0, 330)
    }
    int arow[2];
#pragma unroll
    for (int m = 0; m < 2; m++) arow[m] = warp_m * 32 + m * 16 + (lane & 15);

    // A tile: 128 rows x 8 uint4; 4 slots per thread
    const int ac = tid & 7;
    uint32_t adof[4];
#pragma unroll
    for (int i = 0; i < 4; i++) {
        int ar = (tid >> 3) + i * 32;
        adof[i] = ar * 128 + ((ac ^ (ar & 7)) << 4);
    }

    auto fetch_A = [&](int cs, uint4* regs) {
        const int chunk = cs / 9, shift = cs - chunk * 9;
#pragma unroll
        for (int i = 0; i < 4; i++) {
            int row = (tid >> 3) + i * 32;
            regs[i] = *(const uint4*)((const char*)wgt +
                (((size_t)(shift * CoPad + co0 + row)) * 256 + chunk * 64) * 2 + ac * 16);
        }
    };
    auto store_A = [&](const uint4* regs) {
#pragma unroll
        for (int i = 0; i < 4; i++)
            *(uint4*)(smem + A_OFF + adof[i]) = regs[i];
    };
    auto load_B = [&](int chunk) {
        const int prem = PPIX_ - pmin;
        const size_t gb = (((size_t)t * PPIX_ + pmin) * 256 + chunk * 64) * 2;
#pragma unroll
        for (int i = 0; i < 11; i++) {
            int idx = tid + i * 256;
            if (idx < BROWS * 8) {
                int r = idx >> 3, c = idx & 7;
                uint32_t dof = r * 128 + ((c ^ (r & 7)) << 4);
                uint4 vh = make_uint4(0, 0, 0, 0), vl = make_uint4(0, 0, 0, 0);
                if (r < prem) {
                    vh = *(const uint4*)((const char*)xh + gb + (size_t)r * 512 + c * 16);
                    vl = *(const uint4*)((const char*)xl + gb + (size_t)r * 512 + c * 16);
                }
                *(uint4*)(smem + BH_OFF + dof) = vh;
                *(uint4*)(smem + BL_OFF + dof) = vl;
            }
        }
    };

    // prologue
    load_B(0);
    {
        uint4 a0[4];
        fetch_A(0, a0);
        store_A(a0);
    }
    __syncthreads();

    for (int cs = 0; cs < 36; cs++) {
        const int shift = cs % 9;
        uint4 apre[4];
        if (cs + 1 < 36) fetch_A(cs + 1, apre);

        const uint32_t AS = sb + A_OFF;
        const int off = (shift / 3 - 1) * PW_ + (shift % 3 - 1);
#pragma unroll
        for (int ks = 0; ks < 4; ks++) {
            uint32_t a[2][4], b[4][4];
#pragma unroll
            for (int m = 0; m < 2; m++) {
                int c = ks * 2 + kh_a;
                ldsm4(a[m], AS + arow[m] * 128 + ((c ^ (arow[m] & 7)) << 4));
            }
            // W * Xl
#pragma unroll
            for (int j = 0; j < 4; j++) {
                int r = prow[j] + off;
                int c = ks * 2 + kh_b;
                ldsm4(b[j], sb + BL_OFF + r * 128 + ((c ^ (r & 7)) << 4));
            }
#pragma unroll
            for (int m = 0; m < 2; m++)
#pragma unroll
                for (int n = 0; n < 8; n++)
                    mma16816(C[m][n], a[m], b[n >> 1][(n & 1) * 2], b[n >> 1][(n & 1) * 2 + 1]);
            // W * Xh
#pragma unroll
            for (int j = 0; j < 4; j++) {
                int r = prow[j] + off;
                int c = ks * 2 + kh_b;
                ldsm4(b[j], sb + BH_OFF + r * 128 + ((c ^ (r & 7)) << 4));
            }
#pragma unroll
            for (int m = 0; m < 2; m++)
#pragma unroll
                for (int n = 0; n < 8; n++)
                    mma16816(C[m][n], a[m], b[n >> 1][(n & 1) * 2], b[n >> 1][(n & 1) * 2 + 1]);
        }

        __syncthreads();                         // all ldsm of A/B done
        if (cs + 1 < 36) store_A(apre);          // overwrite single A stage
        if (shift == 8 && cs + 1 < 36) load_B(cs / 9 + 1);
        __syncthreads();                         // new A/B visible
    }

    // epilogue
#pragma unroll
    for (int m = 0; m < 2; m++) {
        const int coA = co0 + warp_m * 32 + m * 16 + (lane >> 2);
#pragma unroll
        for (int n = 0; n < 8; n++) {
            const int px = o0 + warp_n * 64 + n * 8 + ((lane & 3) << 1);
#pragma unroll
            for (int half = 0; half < 2; half++) {
                const int co = coA + half * 8;
                const float v0 = C[m][n][half * 2 + 0];
                const float v1 = C[m][n][half * 2 + 1];
                if (layout == 0) {
                    const float bv = bias1[co];
                    float* op = out + ((size_t)t * Cout1 + co) * HW_ + px;
                    op[0] = v0 + bv; op[1] = v1 + bv;
                } else if (layout == 1) {
                    const float bv = bias1[co];
                    const int head = co >> 5, dh = co & 31;
                    __half* op = g_value + (((size_t)(t * 8 + head) * HW_ + px) << 5) + dh;
                    op[0]  = __float2half(v0 + bv);
                    op[32] = __float2half(v1 + bv);
                } else {
                    if (co < 480) {
                        float bv; float* op;
                        if (co < 320) { bv = bias1[co];       op = g_off  + ((size_t)t * 320 + co)       * HW_ + px; }
                        else          { bv = bias2[co - 320]; op = g_attn + ((size_t)t * 160 + co - 320) * HW_ + px; }
                        op[0] = v0 + bv; op[1] = v1 + bv;
                    }
                }
            }
        }
    }
}

// merged value(x<2) + off/attn(x>=2) conv
__global__ void __launch_bounds__(256, 2) conv_main_kernel(
    const float* __restrict__ b_val, const float* __restrict__ b_off, const float* __restrict__ b_attn)
{
    extern __shared__ char smem[];
    if (blockIdx.x < 2)
        conv_body(smem, g_wv, g_xfh, g_xfl, b_val, nullptr, nullptr, 256, 256, 1, (int)blockIdx.x << 7);
    else
        conv_body(smem, g_wp, g_xqh, g_xql, b_off, b_attn, nullptr, 320, 512, 2, ((int)blockIdx.x - 2) << 7);
}

__global__ void __launch_bounds__(256, 2) conv_out_kernel(
    const float* __restrict__ b_out, float* __restrict__ out)
{
    extern __shared__ char smem[];
    conv_body(smem, g_wu, g_xsh, g_xsl, b_out, nullptr, out, 256, 256, 0, (int)blockIdx.x << 7);
}

// ================= fused flow composition (single block) =================
__constant__ int c_flow_steps[9][3] = {
    {1,  7,  2},   // f02
    {2, 13,  3},   // f03
    {3, 19,  4},   // f04
    {7, 13,  8},   // f13
    {8, 19,  9},   // f14
    {13, 19, 14},  // f24
    {11, 5, 10},   // b20
    {17, 11, 16},  // b31
    {16, 5, 15},   // b30
};

__global__ void __launch_bounds__(1024) flow_all_kernel(
    const float* __restrict__ ff, const float* __restrict__ fb)
{
    const int tid = threadIdx.x;
    for (int p = tid; p < HW_; p += 1024) {
#pragma unroll
        for (int i = 0; i < 4; i++)
#pragma unroll
            for (int j = 0; j < 5; j++) {
                g_adds[((i * 5 + j) * 2 + 0) * HW_ + p] = 0.f;
                g_adds[((i * 5 + j) * 2 + 1) * HW_ + p] = 0.f;
            }
#pragma unroll
        for (int k = 0; k < 4; k++) {
            g_adds[((k * 5 + (k + 1)) * 2 + 0) * HW_ + p] = ff[(k * 2 + 0) * HW_ + p];
            g_adds[((k * 5 + (k + 1)) * 2 + 1) * HW_ + p] = ff[(k * 2 + 1) * HW_ + p];
        }
#pragma unroll
        for (int k = 0; k < 3; k++) {
            g_adds[(((k + 1) * 5 + k) * 2 + 0) * HW_ + p] = fb[(k * 2 + 0) * HW_ + p];
            g_adds[(((k + 1) * 5 + k) * 2 + 1) * HW_ + p] = fb[(k * 2 + 1) * HW_ + p];
        }
    }
    __syncthreads();
    for (int step = 0; step < 9; step++) {
        const float* bptr = g_adds + c_flow_steps[step][0] * 2 * HW_;
        const float* tgt  = g_adds + c_flow_steps[step][1] * 2 * HW_;
        float*       dst  = g_adds + c_flow_steps[step][2] * 2 * HW_;
        for (int p = tid; p < HW_; p += 1024) {
            int y = p / W_, x = p - y * W_;
            float fx = bptr[p], fy = bptr[HW_ + p];
            float px = (float)x + fx, py = (float)y + fy;
            float x0f = floorf(px), y0f = floorf(py);
            int   x0 = (int)x0f, y0 = (int)y0f;
            float wx1 = px - x0f, wx0 = 1.f - wx1;
            float wy1 = py - y0f, wy0 = 1.f - wy1;
            float s0 = 0.f, s1 = 0.f;
            const int xs[4] = {x0, x0 + 1, x0, x0 + 1};
            const int ys[4] = {y0, y0, y0 + 1, y0 + 1};
            const float ws[4] = {wx0 * wy0, wx1 * wy0, wx0 * wy1, wx1 * wy1};
#pragma unroll
            for (int k = 0; k < 4; k++) {
                if ((unsigned)xs[k] < W_ && (unsigned)ys[k] < H_) {
                    int idx = ys[k] * W_ + xs[k];
                    s0 = fmaf(tgt[idx], ws[k], s0);
                    s1 = fmaf(tgt[HW_ + idx], ws[k], s1);
                }
            }
            dst[p]       = fx + s0;
            dst[HW_ + p] = fy + s1;
        }
        __syncthreads();
    }
}

// ================= deformable sampling (fp16 value cache) =================
__global__ void __launch_bounds__(256) sample_kernel(const float* __restrict__ ref_pts)
{
    const int item = blockIdx.x * 8 + (threadIdx.x >> 5);
    const int lane = threadIdx.x & 31;
    const int head = item & 7;
    const int q    = item >> 3;
    const int t    = q / HW_;
    const int p    = q - t * HW_;
    const int ri   = (t == 4) ? 3 : t;

    const float* attn_base = g_attn + (size_t)t * 160 * HW_ + (size_t)head * 20 * HW_ + p;
    float lg[20];
    float mx = -1e30f;
#pragma unroll
    for (int i = 0; i < 20; i++) { lg[i] = attn_base[(size_t)i * HW_]; mx = fmaxf(mx, lg[i]); }
    float ssum = 0.f;
#pragma unroll
    for (int i = 0; i < 20; i++) { lg[i] = __expf(lg[i] - mx); ssum += lg[i]; }
    const float inv = 1.f / ssum;

    const float* off_base = g_off + (size_t)t * 320 * HW_ + p;
    float outv = 0.f;
#pragma unroll
    for (int l = 0; l < LVLS_; l++) {
        const float ax = g_adds[((ri * 5 + l) * 2 + 0) * HW_ + p];
        const float ay = g_adds[((ri * 5 + l) * 2 + 1) * HW_ + p];
        const float rx = ref_pts[((size_t)q * 5 + l) * 2 + 0];
        const float ry = ref_pts[((size_t)q * 5 + l) * 2 + 1];
        const __half* vimg = g_value + ((size_t)(l * 8 + head) * HW_ << 5) + lane;
#pragma unroll
        for (int pt = 0; pt < PTS_; pt++) {
            const int ch = ((head * 5 + l) * 4 + pt) * 2;
            const float ox = off_base[(size_t)ch * HW_] + ax;
            const float oy = off_base[(size_t)(ch + 1) * HW_] + ay;
            const float px = fmaf(rx, (float)W_, ox) - 0.5f;
            const float py = fmaf(ry, (float)H_, oy) - 0.5f;
            const float x0f = floorf(px), y0f = floorf(py);
            const int   x0 = (int)x0f, y0 = (int)y0f;
            const float wx1 = px - x0f, wx0 = 1.f - wx1;
            const float wy1 = py - y0f, wy0 = 1.f - wy1;
            float s = 0.f;
            const bool vx0 = (unsigned)x0 < W_,       vx1 = (unsigned)(x0 + 1) < W_;
            const bool vy0 = (unsigned)y0 < H_,       vy1 = (unsigned)(y0 + 1) < H_;
            if (vy0) {
                const long long r0 = (long long)y0 * W_;
                if (vx0) s = fmaf(__half2float(vimg[(r0 + x0) << 5]),     wx0 * wy0, s);
                if (vx1) s = fmaf(__half2float(vimg[(r0 + x0 + 1) << 5]), wx1 * wy0, s);
            }
            if (vy1) {
                const long long r1 = (long long)(y0 + 1) * W_;
                if (vx0) s = fmaf(__half2float(vimg[(r1 + x0) << 5]),     wx0 * wy1, s);
                if (vx1) s = fmaf(__half2float(vimg[(r1 + x0 + 1) << 5]), wx1 * wy1, s);
            }
            outv = fmaf(s, lg[l * 4 + pt] * inv, outv);
        }
    }
    const int y = p / 96, x = p - y * 96;
    const size_t ob = ((size_t)t * PPIX_ + (size_t)(y + 1) * PW_ + x + 1) * 256 + (head << 5) + lane;
    __half h = __float2half(outv);
    g_xsh[ob] = h;
    g_xsl[ob] = __float2half(outv - __half2float(h));
}

// ================= launch =================
extern "C" void kernel_launch(void* const* d_in, const int* in_sizes, int n_in,
                              void* d_out, int out_size)
{
    (void)in_sizes; (void)n_in; (void)out_size;
    const float* query         = (const float*)d_in[0];
    const float* input_flatten = (const float*)d_in[1];
    const float* ref_pts       = (const float*)d_in[2];
    const float* ff     = (const float*)d_in[6];
    const float* fb     = (const float*)d_in[7];
    const float* w_off  = (const float*)d_in[8];
    const float* b_off  = (const float*)d_in[9];
    const float* w_attn = (const float*)d_in[10];
    const float* b_attn = (const float*)d_in[11];
    const float* w_val  = (const float*)d_in[12];
    const float* b_val  = (const float*)d_in[13];
    const float* w_out  = (const float*)d_in[14];
    const float* b_out  = (const float*)d_in[15];
    float* out = (float*)d_out;

    cudaFuncSetAttribute(conv_main_kernel, cudaFuncAttributeMaxDynamicSharedMemorySize, SMTOT);
    cudaFuncSetAttribute(conv_out_kernel,  cudaFuncAttributeMaxDynamicSharedMemorySize, SMTOT);

    // device addresses of __device__ symbols (NEVER pass symbols directly as args)
    __half *xfh, *xfl, *xqh, *xql, *wv, *wp, *wu;
    cudaGetSymbolAddress((void**)&xfh, g_xfh); cudaGetSymbolAddress((void**)&xfl, g_xfl);
    cudaGetSymbolAddress((void**)&xqh, g_xqh); cudaGetSymbolAddress((void**)&xql, g_xql);
    cudaGetSymbolAddress((void**)&wv, g_wv);
    cudaGetSymbolAddress((void**)&wp, g_wp);
    cudaGetSymbolAddress((void**)&wu, g_wu);

    // ---- preps ----
    zero_border_kernel<<<(T_ * PPIX_ * 32 + 255) / 256, 256>>>();
    prep_x_kernel<<<dim3(64, 5), 128>>>(input_flatten, xfh, xfl);
    prep_x_kernel<<<dim3(64, 5), 128>>>(query, xqh, xql);
    prep_w_kernel<<<(256 * 256 * 9 + 255) / 256, 256>>>(w_val, 256, nullptr, 0, 256, wv);
    prep_w_kernel<<<(512 * 256 * 9 + 255) / 256, 256>>>(w_off, 320, w_attn, 160, 512, wp);
    prep_w_kernel<<<(256 * 256 * 9 + 255) / 256, 256>>>(w_out, 256, nullptr, 0, 256, wu);

    // ---- flow composition ----
    flow_all_kernel<<<1, 1024>>>(ff, fb);

    // ---- merged value + off/attn convs ----
    conv_main_kernel<<<dim3(6, 48, 5), 256, SMTOT>>>(b_val, b_off, b_attn);

    // ---- deformable attention sampling ----
    sample_kernel<<<(T_ * HW_ * HEADS_) / 8, 256>>>(ref_pts);

    // ---- output projection ----
    conv_out_kernel<<<dim3(2, 48, 5), 256, SMTOT>>>(b_out, out);
}

// round 10
// speedup vs baseline: 1.5338x; 1.1986x over previous
#include <cuda_runtime.h>
#include <cuda_fp16.h>
#include <cstdint>
#include <math.h>

#define T_ 5
#define H_ 64
#define W_ 96
#define HW_ (H_ * W_)
#define HEADS_ 8
#define LVLS_ 5
#define PTS_ 4
#define NPIX_ (T_ * HW_)
#define PW_ (W_ + 2)            // 98
#define PH_ (H_ + 2)            // 66
#define PPIX_ (PW_ * PH_)       // 6468

// ================= helpers =================
__device__ __forceinline__ uint32_t smem_u32(const void* p) {
    uint32_t a;
    asm("{ .reg .u64 t; cvta.to.shared.u64 t, %1; cvt.u32.u64 %0, t; }" : "=r"(a) : "l"(p));
    return a;
}
__device__ __forceinline__ void ldsm4(uint32_t* r, uint32_t addr) {
    asm volatile("ldmatrix.sync.aligned.m8n8.x4.shared.b16 {%0,%1,%2,%3}, [%4];"
        : "=r"(r[0]), "=r"(r[1]), "=r"(r[2]), "=r"(r[3]) : "r"(addr));
}
__device__ __forceinline__ void mma16816(float* c, const uint32_t* a, uint32_t b0, uint32_t b1) {
    asm volatile(
        "mma.sync.aligned.m16n8k16.row.col.f32.f16.f16.f32 "
        "{%0,%1,%2,%3}, {%4,%5,%6,%7}, {%8,%9}, {%0,%1,%2,%3};"
        : "+f"(c[0]), "+f"(c[1]), "+f"(c[2]), "+f"(c[3])
        : "r"(a[0]), "r"(a[1]), "r"(a[2]), "r"(a[3]), "r"(b0), "r"(b1));
}
// cp.async 16B with zero-fill when !ok
__device__ __forceinline__ void cp16(uint32_t dst, const void* src, int ok) {
    asm volatile(
        "{\n\t.reg .pred p;\n\tsetp.ne.s32 p, %2, 0;\n\t"
        "@p cp.async.cg.shared.global [%0], [%1], 16;\n\t"
        "@!p cp.async.cg.shared.global [%0], [%1], 16, 0;\n\t}"
        :: "r"(dst), "l"(src), "r"(ok) : "memory");
}
__device__ __forceinline__ void cp_async_wait_all() {
    asm volatile("cp.async.commit_group;\ncp.async.wait_group 0;" ::: "memory");
}

// ================= scratch =================
__device__ __align__(16) __half g_xfh[(size_t)T_ * PPIX_ * 256], g_xfl[(size_t)T_ * PPIX_ * 256];
__device__ __align__(16) __half g_xqh[(size_t)T_ * PPIX_ * 256], g_xql[(size_t)T_ * PPIX_ * 256];
__device__ __align__(16) __half g_xsh[(size_t)T_ * PPIX_ * 256], g_xsl[(size_t)T_ * PPIX_ * 256];
__device__ __align__(16) __half g_wv[9 * 256 * 256];
__device__ __align__(16) __half g_wp[9 * 512 * 256];   // off+attn fused
__device__ __align__(16) __half g_wu[9 * 256 * 256];
__device__ __align__(16) __half g_value[(size_t)T_ * HEADS_ * HW_ * 32];   // [t][head][pix][dh]
__device__ float g_off  [(size_t)T_ * 320 * HW_];
__device__ float g_attn [(size_t)T_ * 160 * HW_];
__device__ float g_adds [(size_t)4 * 5 * 2 * HW_];

// ================= merged input prep: transpose + split + border zeroing =================
// grid (65, 5, 2): x<64 -> interior row-block transpose; x==64 -> border zeroing.
// z=0: input_flatten -> (g_xfh, g_xfl)  [+ zero borders of xf AND xs]
// z=1: query         -> (g_xqh, g_xql)  [+ zero borders of xq]
__global__ void __launch_bounds__(128) prep_x_all_kernel(
    const float* __restrict__ src0, const float* __restrict__ src1)
{
    const int t = blockIdx.y, z = blockIdx.z, tid = threadIdx.x;
    __half* dh = z ? g_xqh : g_xfh;
    __half* dl = z ? g_xql : g_xfl;

    if (blockIdx.x == 64) {   // border zeroing for this t
        for (int pp = tid; pp < PPIX_; pp += 128) {
            int py = pp / PW_, px = pp - py * PW_;
            if (py == 0 || py == PH_ - 1 || px == 0 || px == PW_ - 1) {
                size_t o = ((size_t)t * PPIX_ + pp) * 256;   // half elements
                uint4 z4 = make_uint4(0, 0, 0, 0);
#pragma unroll
                for (int c = 0; c < 32; c++) {
                    *(uint4*)((char*)dh + (o + c * 8) * 2) = z4;
                    *(uint4*)((char*)dl + (o + c * 8) * 2) = z4;
                    if (z == 0) {
                        *(uint4*)((char*)g_xsh + (o + c * 8) * 2) = z4;
                        *(uint4*)((char*)g_xsl + (o + c * 8) * 2) = z4;
                    }
                }
            }
        }
        return;
    }

    const float* src = z ? src1 : src0;
    const int y = blockIdx.x;
    __shared__ float s[64][97];
    for (int cib = 0; cib < 4; cib++) {
        __syncthreads();
        for (int i = tid; i < 64 * 96; i += 128) {
            int r = i / 96, c = i - r * 96;
            s[r][c] = src[((size_t)(t * 256 + cib * 64 + r)) * HW_ + y * 96 + c];
        }
        __syncthreads();
        if (tid < 96) {
            size_t ob = ((size_t)t * PPIX_ + (size_t)(y + 1) * PW_ + tid + 1) * 256 + cib * 64;
#pragma unroll 8
            for (int ci = 0; ci < 64; ci++) {
                float v = s[ci][tid];
                __half h = __float2half(v);
                dh[ob + ci] = h;
                dl[ob + ci] = __float2half(v - __half2float(h));
            }
        }
    }
}

// ================= merged weight prep (all three tensors) =================
// co_all in [0,1024): [0,256)=wv(w_val), [256,768)=wp(w_off|w_attn), [768,1024)=wu(w_out)
__global__ void prep_w_all_kernel(
    const float* __restrict__ w_val, const float* __restrict__ w_off,
    const float* __restrict__ w_attn, const float* __restrict__ w_out)
{
    int idx = blockIdx.x * 256 + threadIdx.x;
    if (idx >= 9 * 1024 * 256) return;
    int ci = idx & 255;
    int rest = idx >> 8;
    int co_all = rest & 1023;
    int shift = rest >> 10;
    if (co_all < 256) {
        g_wv[((size_t)(shift * 256 + co_all)) * 256 + ci] =
            __float2half(w_val[((size_t)co_all * 256 + ci) * 9 + shift]);
    } else if (co_all < 768) {
        int c2 = co_all - 256;
        float v = (c2 < 320) ? w_off[((size_t)c2 * 256 + ci) * 9 + shift]
                             : w_attn[((size_t)(c2 - 320) * 256 + ci) * 9 + shift];
        g_wp[((size_t)(shift * 512 + c2)) * 256 + ci] = __float2half(v);
    } else {
        int c3 = co_all - 768;
        g_wu[((size_t)(shift * 256 + c3)) * 256 + ci] =
            __float2half(w_out[((size_t)c3 * 256 + ci) * 9 + shift]);
    }
}

// ================= HMMA implicit-GEMM 3x3 conv (128co x 128pix, occ 2) =================
#define BROWS  330
#define BBYTES (BROWS * 128)            // 42240
#define BH_OFF 0
#define BL_OFF BBYTES                   // 42240
#define A_OFF  (2 * BBYTES)             // 84480 (128B aligned)
#define SMTOT  (2 * BBYTES + 16384)     // 100864

__device__ __forceinline__ void conv_body(char* smem,
    const __half* __restrict__ wgt,
    const __half* __restrict__ xh, const __half* __restrict__ xl,
    const float* __restrict__ bias1, const float* __restrict__ bias2,
    float* __restrict__ out, int Cout1, int CoPad, int layout, int co0)
{
    const uint32_t sb = smem_u32(smem);
    const int tid = threadIdx.x, wid = tid >> 5, lane = tid & 31;
    const int warp_m = wid & 3, warp_n = wid >> 2;           // 4 co-warps x 2 pix-warps
    const int t = blockIdx.z, o0 = blockIdx.y << 7;          // 128-pixel tile
    const int pmin = o0 + 2 * (o0 / 96);

    float C[2][8][4];
#pragma unroll
    for (int m = 0; m < 2; m++)
#pragma unroll
        for (int n = 0; n < 8; n++)
#pragma unroll
            for (int k = 0; k < 4; k++) C[m][n][k] = 0.f;

    const int kh_b = (lane >> 3) & 1;
    const int kh_a = lane >> 4;
    int prow[4];
#pragma unroll
    for (int j = 0; j < 4; j++) {
        int nl = warp_n * 64 + j * 16 + ((lane >> 4) << 3) + (lane & 7);
        int o = o0 + nl;
        prow[j] = o + 2 * (o / 96) + 99 - pmin;     // in [99, 229); +off stays in [0, 330)
    }
    int arow[2];
#pragma unroll
    for (int m = 0; m < 2; m++) arow[m] = warp_m * 32 + m * 16 + (lane & 15);

    // A tile: 128 rows x 8 uint4; 4 slots per thread
    const int ac = tid & 7;
    uint32_t adof[4];
#pragma unroll
    for (int i = 0; i < 4; i++) {
        int ar = (tid >> 3) + i * 32;
        adof[i] = ar * 128 + ((ac ^ (ar & 7)) << 4);
    }

    auto fetch_A = [&](int cs, uint4* regs) {
        const int chunk = cs / 9, shift = cs - chunk * 9;
#pragma unroll
        for (int i = 0; i < 4; i++) {
            int row = (tid >> 3) + i * 32;
            regs[i] = *(const uint4*)((const char*)wgt +
                (((size_t)(shift * CoPad + co0 + row)) * 256 + chunk * 64) * 2 + ac * 16);
        }
    };
    auto store_A = [&](const uint4* regs) {
#pragma unroll
        for (int i = 0; i < 4; i++)
            *(uint4*)(smem + A_OFF + adof[i]) = regs[i];
    };
    auto load_B = [&](int chunk) {
        const int prem = PPIX_ - pmin;
        const char* bh = (const char*)xh + (((size_t)t * PPIX_ + pmin) * 256 + chunk * 64) * 2;
        const char* bl = (const char*)xl + (((size_t)t * PPIX_ + pmin) * 256 + chunk * 64) * 2;
#pragma unroll
        for (int i = 0; i < 11; i++) {
            int idx = tid + i * 256;
            if (idx < BROWS * 8) {
                int r = idx >> 3, c = idx & 7;
                uint32_t dof = r * 128 + ((c ^ (r & 7)) << 4);
                int ok = (r < prem);
                int rs = ok ? r : 0;
                cp16(sb + BH_OFF + dof, bh + (size_t)rs * 512 + c * 16, ok);
                cp16(sb + BL_OFF + dof, bl + (size_t)rs * 512 + c * 16, ok);
            }
        }
    };

    // prologue
    load_B(0);
    {
        uint4 a0[4];
        fetch_A(0, a0);
        store_A(a0);
    }
    cp_async_wait_all();
    __syncthreads();

    for (int cs = 0; cs < 36; cs++) {
        const int shift = cs % 9;
        uint4 apre[4];
        if (cs + 1 < 36) fetch_A(cs + 1, apre);

        const uint32_t AS = sb + A_OFF;
        const int off = (shift / 3 - 1) * PW_ + (shift % 3 - 1);
#pragma unroll
        for (int ks = 0; ks < 4; ks++) {
            uint32_t a[2][4], b[4][4];
#pragma unroll
            for (int m = 0; m < 2; m++) {
                int c = ks * 2 + kh_a;
                ldsm4(a[m], AS + arow[m] * 128 + ((c ^ (arow[m] & 7)) << 4));
            }
            // W * Xl
#pragma unroll
            for (int j = 0; j < 4; j++) {
                int r = prow[j] + off;
                int c = ks * 2 + kh_b;
                ldsm4(b[j], sb + BL_OFF + r * 128 + ((c ^ (r & 7)) << 4));
            }
#pragma unroll
            for (int m = 0; m < 2; m++)
#pragma unroll
                for (int n = 0; n < 8; n++)
                    mma16816(C[m][n], a[m], b[n >> 1][(n & 1) * 2], b[n >> 1][(n & 1) * 2 + 1]);
            // W * Xh
#pragma unroll
            for (int j = 0; j < 4; j++) {
                int r = prow[j] + off;
                int c = ks * 2 + kh_b;
                ldsm4(b[j], sb + BH_OFF + r * 128 + ((c ^ (r & 7)) << 4));
            }
#pragma unroll
            for (int m = 0; m < 2; m++)
#pragma unroll
                for (int n = 0; n < 8; n++)
                    mma16816(C[m][n], a[m], b[n >> 1][(n & 1) * 2], b[n >> 1][(n & 1) * 2 + 1]);
        }

        __syncthreads();                         // all ldsm of A/B done
        if (cs + 1 < 36) store_A(apre);          // overwrite single A stage
        if (shift == 8 && cs + 1 < 36) {
            load_B(cs / 9 + 1);
            cp_async_wait_all();
        }
        __syncthreads();                         // new A/B visible
    }

    // epilogue
#pragma unroll
    for (int m = 0; m < 2; m++) {
        const int coA = co0 + warp_m * 32 + m * 16 + (lane >> 2);
#pragma unroll
        for (int n = 0; n < 8; n++) {
            const int px = o0 + warp_n * 64 + n * 8 + ((lane & 3) << 1);
#pragma unroll
            for (int half = 0; half < 2; half++) {
                const int co = coA + half * 8;
                const float v0 = C[m][n][half * 2 + 0];
                const float v1 = C[m][n][half * 2 + 1];
                if (layout == 0) {
                    const float bv = bias1[co];
                    float* op = out + ((size_t)t * Cout1 + co) * HW_ + px;
                    op[0] = v0 + bv; op[1] = v1 + bv;
                } else if (layout == 1) {
                    const float bv = bias1[co];
                    const int head = co >> 5, dh = co & 31;
                    __half* op = g_value + (((size_t)(t * 8 + head) * HW_ + px) << 5) + dh;
                    op[0]  = __float2half(v0 + bv);
                    op[32] = __float2half(v1 + bv);
                } else {
                    if (co < 480) {
                        float bv; float* op;
                        if (co < 320) { bv = bias1[co];       op = g_off  + ((size_t)t * 320 + co)       * HW_ + px; }
                        else          { bv = bias2[co - 320]; op = g_attn + ((size_t)t * 160 + co - 320) * HW_ + px; }
                        op[0] = v0 + bv; op[1] = v1 + bv;
                    }
                }
            }
        }
    }
}

// merged value(x<2) + off/attn(x>=2) conv
__global__ void __launch_bounds__(256, 2) conv_main_kernel(
    const float* __restrict__ b_val, const float* __restrict__ b_off, const float* __restrict__ b_attn)
{
    extern __shared__ char smem[];
    if (blockIdx.x < 2)
        conv_body(smem, g_wv, g_xfh, g_xfl, b_val, nullptr, nullptr, 256, 256, 1, (int)blockIdx.x << 7);
    else
        conv_body(smem, g_wp, g_xqh, g_xql, b_off, b_attn, nullptr, 320, 512, 2, ((int)blockIdx.x - 2) << 7);
}

__global__ void __launch_bounds__(256, 2) conv_out_kernel(
    const float* __restrict__ b_out, float* __restrict__ out)
{
    extern __shared__ char smem[];
    conv_body(smem, g_wu, g_xsh, g_xsl, b_out, nullptr, out, 256, 256, 0, (int)blockIdx.x << 7);
}

// ================= fused flow composition (single block) =================
__constant__ int c_flow_steps[9][3] = {
    {1,  7,  2},   // f02
    {2, 13,  3},   // f03
    {3, 19,  4},   // f04
    {7, 13,  8},   // f13
    {8, 19,  9},   // f14
    {13, 19, 14},  // f24
    {11, 5, 10},   // b20
    {17, 11, 16},  // b31
    {16, 5, 15},   // b30
};

__global__ void __launch_bounds__(1024) flow_all_kernel(
    const float* __restrict__ ff, const float* __restrict__ fb)
{
    const int tid = threadIdx.x;
    for (int p = tid; p < HW_; p += 1024) {
#pragma unroll
        for (int i = 0; i < 4; i++)
#pragma unroll
            for (int j = 0; j < 5; j++) {
                g_adds[((i * 5 + j) * 2 + 0) * HW_ + p] = 0.f;
                g_adds[((i * 5 + j) * 2 + 1) * HW_ + p] = 0.f;
            }
#pragma unroll
        for (int k = 0; k < 4; k++) {
            g_adds[((k * 5 + (k + 1)) * 2 + 0) * HW_ + p] = ff[(k * 2 + 0) * HW_ + p];
            g_adds[((k * 5 + (k + 1)) * 2 + 1) * HW_ + p] = ff[(k * 2 + 1) * HW_ + p];
        }
#pragma unroll
        for (int k = 0; k < 3; k++) {
            g_adds[(((k + 1) * 5 + k) * 2 + 0) * HW_ + p] = fb[(k * 2 + 0) * HW_ + p];
            g_adds[(((k + 1) * 5 + k) * 2 + 1) * HW_ + p] = fb[(k * 2 + 1) * HW_ + p];
        }
    }
    __syncthreads();
    for (int step = 0; step < 9; step++) {
        const float* bptr = g_adds + c_flow_steps[step][0] * 2 * HW_;
        const float* tgt  = g_adds + c_flow_steps[step][1] * 2 * HW_;
        float*       dst  = g_adds + c_flow_steps[step][2] * 2 * HW_;
        for (int p = tid; p < HW_; p += 1024) {
            int y = p / W_, x = p - y * W_;
            float fx = bptr[p], fy = bptr[HW_ + p];
            float px = (float)x + fx, py = (float)y + fy;
            float x0f = floorf(px), y0f = floorf(py);
            int   x0 = (int)x0f, y0 = (int)y0f;
            float wx1 = px - x0f, wx0 = 1.f - wx1;
            float wy1 = py - y0f, wy0 = 1.f - wy1;
            float s0 = 0.f, s1 = 0.f;
            const int xs[4] = {x0, x0 + 1, x0, x0 + 1};
            const int ys[4] = {y0, y0, y0 + 1, y0 + 1};
            const float ws[4] = {wx0 * wy0, wx1 * wy0, wx0 * wy1, wx1 * wy1};
#pragma unroll
            for (int k = 0; k < 4; k++) {
                if ((unsigned)xs[k] < W_ && (unsigned)ys[k] < H_) {
                    int idx = ys[k] * W_ + xs[k];
                    s0 = fmaf(tgt[idx], ws[k], s0);
                    s1 = fmaf(tgt[HW_ + idx], ws[k], s1);
                }
            }
            dst[p]       = fx + s0;
            dst[HW_ + p] = fy + s1;
        }
        __syncthreads();
    }
}

// ================= deformable sampling (fp16 value cache) =================
__global__ void __launch_bounds__(256) sample_kernel(const float* __restrict__ ref_pts)
{
    const int item = blockIdx.x * 8 + (threadIdx.x >> 5);
    const int lane = threadIdx.x & 31;
    const int head = item & 7;
    const int q    = item >> 3;
    const int t    = q / HW_;
    const int p    = q - t * HW_;
    const int ri   = (t == 4) ? 3 : t;

    const float* attn_base = g_attn + (size_t)t * 160 * HW_ + (size_t)head * 20 * HW_ + p;
    float lg[20];
    float mx = -1e30f;
#pragma unroll
    for (int i = 0; i < 20; i++) { lg[i] = attn_base[(size_t)i * HW_]; mx = fmaxf(mx, lg[i]); }
    float ssum = 0.f;
#pragma unroll
    for (int i = 0; i < 20; i++) { lg[i] = __expf(lg[i] - mx); ssum += lg[i]; }
    const float inv = 1.f / ssum;

    const float* off_base = g_off + (size_t)t * 320 * HW_ + p;
    float outv = 0.f;
#pragma unroll
    for (int l = 0; l < LVLS_; l++) {
        const float ax = g_adds[((ri * 5 + l) * 2 + 0) * HW_ + p];
        const float ay = g_adds[((ri * 5 + l) * 2 + 1) * HW_ + p];
        const float rx = ref_pts[((size_t)q * 5 + l) * 2 + 0];
        const float ry = ref_pts[((size_t)q * 5 + l) * 2 + 1];
        const __half* vimg = g_value + ((size_t)(l * 8 + head) * HW_ << 5) + lane;
#pragma unroll
        for (int pt = 0; pt < PTS_; pt++) {
            const int ch = ((head * 5 + l) * 4 + pt) * 2;
            const float ox = off_base[(size_t)ch * HW_] + ax;
            const float oy = off_base[(size_t)(ch + 1) * HW_] + ay;
            const float px = fmaf(rx, (float)W_, ox) - 0.5f;
            const float py = fmaf(ry, (float)H_, oy) - 0.5f;
            const float x0f = floorf(px), y0f = floorf(py);
            const int   x0 = (int)x0f, y0 = (int)y0f;
            const float wx1 = px - x0f, wx0 = 1.f - wx1;
            const float wy1 = py - y0f, wy0 = 1.f - wy1;
            float s = 0.f;
            const bool vx0 = (unsigned)x0 < W_,       vx1 = (unsigned)(x0 + 1) < W_;
            const bool vy0 = (unsigned)y0 < H_,       vy1 = (unsigned)(y0 + 1) < H_;
            if (vy0) {
                const long long r0 = (long long)y0 * W_;
                if (vx0) s = fmaf(__half2float(vimg[(r0 + x0) << 5]),     wx0 * wy0, s);
                if (vx1) s = fmaf(__half2float(vimg[(r0 + x0 + 1) << 5]), wx1 * wy0, s);
            }
            if (vy1) {
                const long long r1 = (long long)(y0 + 1) * W_;
                if (vx0) s = fmaf(__half2float(vimg[(r1 + x0) << 5]),     wx0 * wy1, s);
                if (vx1) s = fmaf(__half2float(vimg[(r1 + x0 + 1) << 5]), wx1 * wy1, s);
            }
            outv = fmaf(s, lg[l * 4 + pt] * inv, outv);
        }
    }
    const int y = p / 96, x = p - y * 96;
    const size_t ob = ((size_t)t * PPIX_ + (size_t)(y + 1) * PW_ + x + 1) * 256 + (head << 5) + lane;
    __half h = __float2half(outv);
    g_xsh[ob] = h;
    g_xsl[ob] = __float2half(outv - __half2float(h));
}

// ================= launch =================
extern "C" void kernel_launch(void* const* d_in, const int* in_sizes, int n_in,
                              void* d_out, int out_size)
{
    (void)in_sizes; (void)n_in; (void)out_size;
    const float* query         = (const float*)d_in[0];
    const float* input_flatten = (const float*)d_in[1];
    const float* ref_pts       = (const float*)d_in[2];
    const float* ff     = (const float*)d_in[6];
    const float* fb     = (const float*)d_in[7];
    const float* w_off  = (const float*)d_in[8];
    const float* b_off  = (const float*)d_in[9];
    const float* w_attn = (const float*)d_in[10];
    const float* b_attn = (const float*)d_in[11];
    const float* w_val  = (const float*)d_in[12];
    const float* b_val  = (const float*)d_in[13];
    const float* w_out  = (const float*)d_in[14];
    const float* b_out  = (const float*)d_in[15];
    float* out = (float*)d_out;

    cudaFuncSetAttribute(conv_main_kernel, cudaFuncAttributeMaxDynamicSharedMemorySize, SMTOT);
    cudaFuncSetAttribute(conv_out_kernel,  cudaFuncAttributeMaxDynamicSharedMemorySize, SMTOT);

    // 0: merged input prep (transposes + all border zeroing)
    prep_x_all_kernel<<<dim3(65, 5, 2), 128>>>(input_flatten, query);
    // 1: merged weight prep
    prep_w_all_kernel<<<(9 * 1024 * 256 + 255) / 256, 256>>>(w_val, w_off, w_attn, w_out);
    // 2: flow composition
    flow_all_kernel<<<1, 1024>>>(ff, fb);
    // 3: merged value + off/attn convs
    conv_main_kernel<<<dim3(6, 48, 5), 256, SMTOT>>>(b_val, b_off, b_attn);
    // 4: deformable attention sampling
    sample_kernel<<<(T_ * HW_ * HEADS_) / 8, 256>>>(ref_pts);
    // 5: output projection
    conv_out_kernel<<<dim3(2, 48, 5), 256, SMTOT>>>(b_out, out);
}